// round 1
// baseline (speedup 1.0000x reference)
#include <cuda_runtime.h>
#include <math.h>

// Problem constants
#define SX 18           // input spatial size per dim
#define KS 13           // kernel size per dim
#define OS 6            // output spatial size per dim (18-13+1)
#define NC 3            // output channels
#define W4 28561        // 13^4
#define W3 2197         // 13^3
#define W2 169          // 13^2
#define X3 5832         // 18^3
#define X2 324          // 18^2
#define XB 104976       // 18^4

// One block per batch element. 128 threads, 108 active: (c, oy, oz).
// Each active thread accumulates acc[ox][ow] (6x6) over the full 13^4 kernel,
// staged as 169 (ky,kz) iterations with the 3x13x13 weight slab in SMEM.
__global__ __launch_bounds__(128, 4)
void conv4d_fused_kernel(const float* __restrict__ x,
                         const float* __restrict__ cw,
                         const float* __restrict__ cb,
                         const float* __restrict__ lw,
                         const float* __restrict__ lb,
                         float* __restrict__ out)
{
    __shared__ float w_s[NC * KS * KS];   // [c][kx][kw] for current (ky,kz)
    __shared__ float red[128];

    const int b   = blockIdx.x;
    const int tid = threadIdx.x;
    const bool active = (tid < NC * OS * OS);   // 108

    int c = 0, oy = 0, oz = 0;
    if (active) {
        c  = tid / 36;
        int r = tid % 36;
        oy = r / 6;
        oz = r % 6;
    }

    float acc[36];
    #pragma unroll
    for (int i = 0; i < 36; ++i) acc[i] = 0.f;

    const float* xb = x + (size_t)b * XB;

    #pragma unroll 1
    for (int ky = 0; ky < KS; ++ky) {
        #pragma unroll 1
        for (int kz = 0; kz < KS; ++kz) {
            __syncthreads();   // protect previous slab readers
            // Cooperative load of weight slab: w[c][kx][ky][kz][kw], 507 floats
            for (int t = tid; t < NC * W2; t += 128) {
                int cc = t / W2;
                int r  = t % W2;
                int kx = r / KS;
                int kw = r % KS;
                w_s[t] = cw[cc * W4 + kx * W3 + ky * W2 + kz * KS + kw];
            }
            __syncthreads();

            if (active) {
                const int iy = oy + ky;
                const int iz = oz + kz;
                const float* xrow0 = xb + (size_t)iy * X2 + (size_t)iz * SX;
                const float* wc = w_s + c * W2;

                #pragma unroll 1
                for (int ix = 0; ix < SX; ++ix) {
                    // Load one x row (18 floats along W) — 8B-aligned float2s
                    float xv[SX];
                    const float2* xr = (const float2*)(xrow0 + (size_t)ix * X3);
                    #pragma unroll
                    for (int j = 0; j < 9; ++j) {
                        float2 v = __ldg(xr + j);
                        xv[2 * j]     = v.x;
                        xv[2 * j + 1] = v.y;
                    }

                    #pragma unroll
                    for (int ox = 0; ox < OS; ++ox) {
                        int kx = ix - ox;
                        if (kx >= 0 && kx < KS) {
                            const float* wr = wc + kx * KS;
                            #pragma unroll
                            for (int kw = 0; kw < KS; ++kw) {
                                float wv = wr[kw];
                                #pragma unroll
                                for (int ow = 0; ow < OS; ++ow) {
                                    acc[ox * 6 + ow] =
                                        fmaf(wv, xv[kw + ow], acc[ox * 6 + ow]);
                                }
                            }
                        }
                    }
                }
            }
        }
    }

    // Epilogue: bias + ReLU + dot with lin_w (flatten order c,ox,oy,oz,ow)
    float partial = 0.f;
    if (active) {
        const float bias = __ldg(cb + c);
        #pragma unroll
        for (int ox = 0; ox < OS; ++ox) {
            #pragma unroll
            for (int ow = 0; ow < OS; ++ow) {
                float h = acc[ox * 6 + ow] + bias;
                h = fmaxf(h, 0.f);
                int idx = c * 1296 + ox * 216 + oy * 36 + oz * 6 + ow;
                partial = fmaf(h, __ldg(lw + idx), partial);
            }
        }
    }

    red[tid] = partial;
    __syncthreads();
    if (tid < 64) red[tid] += red[tid + 64];
    __syncthreads();
    if (tid < 32) {
        float v = red[tid] + red[tid + 32];
        #pragma unroll
        for (int off = 16; off > 0; off >>= 1)
            v += __shfl_down_sync(0xffffffffu, v, off);
        if (tid == 0) {
            float z = v + __ldg(lb);
            out[b] = 1.f / (1.f + expf(-z));
        }
    }
}

extern "C" void kernel_launch(void* const* d_in, const int* in_sizes, int n_in,
                              void* d_out, int out_size)
{
    const float* x      = (const float*)d_in[0];
    const float* conv_w = (const float*)d_in[1];
    const float* conv_b = (const float*)d_in[2];
    const float* lin_w  = (const float*)d_in[3];
    const float* lin_b  = (const float*)d_in[4];
    float* out = (float*)d_out;

    conv4d_fused_kernel<<<512, 128>>>(x, conv_w, conv_b, lin_w, lin_b, out);
}